// round 10
// baseline (speedup 1.0000x reference)
#include <cuda_runtime.h>
#include <cstdint>

// Fixed shapes
#define TT     16
#define TSPLIT 2
#define FPB    (TT / TSPLIT)      // 8 frames per block
#define HH     1280
#define WW     1280
#define NB     64
#define HW     (HH * WW)          // elements per frame
#define ROWB   (WW * 4)           // 5120 bytes per row
#define NTHR   320                // one float4 (4 cols) per thread
#define NWARP  (NTHR / 32)        // 10 warps
#define NBLK   (HH * TSPLIT)      // 2560 blocks
#define NSLOT  32

__device__ double       g_slots[NSLOT];   // zero at load; reset by last block each replay
__device__ unsigned int g_count = 0u;

__device__ __forceinline__ unsigned smem_u32(const void* p) {
    unsigned a;
    asm("{ .reg .u64 t; cvta.to.shared.u64 t, %1; cvt.u32.u64 %0, t; }" : "=r"(a) : "l"(p));
    return a;
}

// ---------------------------------------------------------------------------
// Block = (row y, t-half). TMA-style bulk-async streaming:
//   1) tid0 inits mbarrier, arrives with expect_tx(40960), issues 8
//      cp.async.bulk copies (one row of 8 frames) into smem
//   2) all warps compute row weights (diff array + block scan) meanwhile
//   3) wait mbarrier; consume smem via LDS.128; weighted dot; reduce
//   4) slot atomics; last block folds slots, writes scalar, resets state
// ---------------------------------------------------------------------------
__global__ void __launch_bounds__(NTHR) fused_kernel(const float* __restrict__ data,
                                                     const int*   __restrict__ boxes,
                                                     float* __restrict__ out) {
    __shared__ __align__(16) float sbuf[FPB * WW];     // 40960 B
    __shared__ int   sdiff[WW];                        // 5120 B
    __shared__ int   wsum[NWARP];
    __shared__ float warp_sums[NWARP];
    __shared__ __align__(8) unsigned long long mbar;

    const int tid  = threadIdx.x;        // 0..319
    const int y    = blockIdx.x;         // row
    const int th   = blockIdx.y;         // t-half
    const int lane = tid & 31;
    const int wid  = tid >> 5;
    const unsigned mb = smem_u32(&mbar);

    if (tid == 0) {
        asm volatile("mbarrier.init.shared.b64 [%0], %1;" :: "r"(mb), "r"(1) : "memory");
    }
    __syncthreads();   // mbarrier visible before TMA targets it

    if (tid == 0) {
        asm volatile("mbarrier.arrive.expect_tx.shared.b64 _, [%0], %1;"
                     :: "r"(mb), "r"(FPB * ROWB) : "memory");
        const char* src0 = reinterpret_cast<const char*>(data)
                           + (size_t)(th * FPB) * HW * 4 + (size_t)y * ROWB;
        unsigned dst = smem_u32(sbuf);
#pragma unroll
        for (int f = 0; f < FPB; f++) {
            asm volatile(
                "cp.async.bulk.shared::cta.global.mbarrier::complete_tx::bytes "
                "[%0], [%1], %2, [%3];"
                :: "r"(dst + f * ROWB),
                   "l"(src0 + (size_t)f * HW * 4),
                   "r"(ROWB), "r"(mb)
                : "memory");
        }
    }

    // ---- weights while copies are in flight: diff array + block scan ----
    reinterpret_cast<int4*>(sdiff)[tid] = make_int4(0, 0, 0, 0);
    __syncthreads();

    if (tid < NB) {
        int4 b = __ldg(reinterpret_cast<const int4*>(boxes) + tid);  // x1,y1,x2,y2
        if (b.y <= y && y < b.w) {
            atomicAdd(&sdiff[b.x],  1);
            atomicAdd(&sdiff[b.z], -1);       // x2 <= 1279 < WW
        }
    }
    __syncthreads();

    int4 c = reinterpret_cast<const int4*>(sdiff)[tid];
    int s0 = c.x, s1 = s0 + c.y, s2 = s1 + c.z, s3 = s2 + c.w;
    const int tot = s3;

    int v = tot;
#pragma unroll
    for (int off = 1; off < 32; off <<= 1) {
        int n = __shfl_up_sync(0xFFFFFFFFu, v, off);
        if (lane >= off) v += n;
    }
    if (lane == 31) wsum[wid] = v;
    __syncthreads();

    int wprefix = 0;
#pragma unroll
    for (int i = 0; i < NWARP; i++)
        if (i < wid) wprefix += wsum[i];
    const int base = wprefix + (v - tot);

    const float w0 = (float)(base + s0);
    const float w1 = (float)(base + s1);
    const float w2 = (float)(base + s2);
    const float w3 = (float)(base + s3);

    // ---- wait for the 8 bulk copies ----
    {
        unsigned done;
        do {
            asm volatile(
                "{ .reg .pred p;\n\t"
                "mbarrier.try_wait.parity.acquire.cta.shared::cta.b64 p, [%1], %2, 0x989680;\n\t"
                "selp.b32 %0, 1, 0, p; }"
                : "=r"(done) : "r"(mb), "r"(0u) : "memory");
        } while (!done);
    }

    // ---- consume smem: 8 frames x float4 per thread ----
    const float4* sb = reinterpret_cast<const float4*>(sbuf);
    float a0 = 0.f, a1 = 0.f, a2 = 0.f, a3 = 0.f;
    float b0 = 0.f, b1 = 0.f, b2 = 0.f, b3 = 0.f;
#pragma unroll
    for (int f = 0; f < FPB; f += 2) {
        float4 qa = sb[(f + 0) * (WW / 4) + tid];
        float4 qb = sb[(f + 1) * (WW / 4) + tid];
        a0 += qa.x; a1 += qa.y; a2 += qa.z; a3 += qa.w;
        b0 += qb.x; b1 += qb.y; b2 += qb.z; b3 += qb.w;
    }

    float s = fmaf(w0, a0 + b0, fmaf(w1, a1 + b1, fmaf(w2, a2 + b2, w3 * (a3 + b3))));

    // ---- warp + block reduce ----
#pragma unroll
    for (int off = 16; off > 0; off >>= 1)
        s += __shfl_down_sync(0xFFFFFFFFu, s, off);
    if (lane == 0) warp_sums[wid] = s;
    __syncthreads();

    if (tid == 0) {
        float bsum = warp_sums[0];
#pragma unroll
        for (int i = 1; i < NWARP; i++) bsum += warp_sums[i];

        atomicAdd(&g_slots[(y + th) & (NSLOT - 1)], (double)bsum);
        __threadfence();
        unsigned old = atomicAdd(&g_count, 1u);
        if (old == NBLK - 1u) {
            __threadfence();
            double total = 0.0;
            volatile double* vs = g_slots;
#pragma unroll
            for (int i = 0; i < NSLOT; i++) {
                total += vs[i];
                vs[i] = 0.0;                  // reset for next graph replay
            }
            out[0] = (float)total;
            __threadfence();
            g_count = 0u;
        }
    }
}

extern "C" void kernel_launch(void* const* d_in, const int* in_sizes, int n_in,
                              void* d_out, int out_size) {
    const float* data  = (const float*)d_in[0];  // (16,1280,1280) fp32
    const int*   boxes = (const int*)d_in[1];    // (64,4) int32 [x1,y1,x2,y2]
    float*       out   = (float*)d_out;

    dim3 grid(HH, TSPLIT);
    fused_kernel<<<grid, NTHR>>>(data, boxes, out);
}

// round 12
// speedup vs baseline: 1.2146x; 1.2146x over previous
#include <cuda_runtime.h>
#include <cstdint>

// Fixed shapes
#define TT    16
#define HH    1280
#define WW    1280
#define NB    64
#define W4    (WW / 4)           // 320 float4 per row
#define HW4   (HH * W4)          // 409,600 float4 per frame
#define NTHR  W4                 // 320 threads: one float4 (4 cols) per thread
#define RPB   2                  // rows per block
#define NBLK  (HH / RPB)         // 640 blocks -> single wave at 6 blocks/SM
#define NWARP (NTHR / 32)        // 10 warps
#define NSLOT 32

__device__ double       g_slots[NSLOT];   // zeroed at load; reset by last block each replay
__device__ unsigned int g_count = 0u;

// ---------------------------------------------------------------------------
// Single-wave kernel: 640 blocks, each handles rows 2b and 2b+1.
// Per row: prefetch 4 frames -> diff-array weight scan (overlapped) ->
// stream remaining 12 frames -> weighted dot folded into a running scalar.
// One block reduce + one spread-slot atomic per block. Last block folds
// slots, writes the scalar output, resets state for the next graph replay.
// ---------------------------------------------------------------------------
__global__ void __launch_bounds__(NTHR, 5) fused_kernel(const float* __restrict__ data,
                                                        const int*   __restrict__ boxes,
                                                        float* __restrict__ out) {
    __shared__ int   sdiff[WW];
    __shared__ int   wsum[NWARP];
    __shared__ float warp_sums[NWARP];

    const int tid  = threadIdx.x;        // 0..319
    const int lane = tid & 31;
    const int wid  = tid >> 5;

    // boxes: one load, reused for both rows
    int4 bx = make_int4(0, 0, 0, 0);
    if (tid < NB) bx = __ldg(reinterpret_cast<const int4*>(boxes) + tid); // x1,y1,x2,y2

    float s = 0.f;

#pragma unroll
    for (int r = 0; r < RPB; r++) {
        const int y = blockIdx.x * RPB + r;

        // ---- prefetch 4 frames (in flight through the scan phase) ----
        const float4* p = reinterpret_cast<const float4*>(data) + (size_t)y * W4 + tid;
        float4 v0 = __ldg(p + 0 * (size_t)HW4);
        float4 v1 = __ldg(p + 1 * (size_t)HW4);
        float4 v2 = __ldg(p + 2 * (size_t)HW4);
        float4 v3 = __ldg(p + 3 * (size_t)HW4);

        // ---- weights: difference array + block scan ----
        reinterpret_cast<int4*>(sdiff)[tid] = make_int4(0, 0, 0, 0);
        __syncthreads();

        if (tid < NB && bx.y <= y && y < bx.w) {
            atomicAdd(&sdiff[bx.x],  1);
            atomicAdd(&sdiff[bx.z], -1);     // x2 <= 1279 < WW
        }
        __syncthreads();

        int4 c = reinterpret_cast<const int4*>(sdiff)[tid];
        int s0 = c.x, s1 = s0 + c.y, s2 = s1 + c.z, s3 = s2 + c.w;
        const int tot = s3;

        int v = tot;
#pragma unroll
        for (int off = 1; off < 32; off <<= 1) {
            int n = __shfl_up_sync(0xFFFFFFFFu, v, off);
            if (lane >= off) v += n;
        }
        if (lane == 31) wsum[wid] = v;
        __syncthreads();

        int wprefix = 0;
#pragma unroll
        for (int i = 0; i < NWARP; i++)
            if (i < wid) wprefix += wsum[i];
        const int base = wprefix + (v - tot);   // exclusive prefix before this thread

        const float w0 = (float)(base + s0);
        const float w1 = (float)(base + s1);
        const float w2 = (float)(base + s2);
        const float w3 = (float)(base + s3);

        // ---- fold prefetched frames ----
        float a0 = (v0.x + v1.x) + (v2.x + v3.x);
        float a1 = (v0.y + v1.y) + (v2.y + v3.y);
        float a2 = (v0.z + v1.z) + (v2.z + v3.z);
        float a3 = (v0.w + v1.w) + (v2.w + v3.w);

        // ---- remaining 12 frames: 3 batches of 4 independent loads ----
#pragma unroll
        for (int t = 4; t < TT; t += 4) {
            float4 q0 = __ldg(p + (size_t)(t + 0) * HW4);
            float4 q1 = __ldg(p + (size_t)(t + 1) * HW4);
            float4 q2 = __ldg(p + (size_t)(t + 2) * HW4);
            float4 q3 = __ldg(p + (size_t)(t + 3) * HW4);
            a0 += (q0.x + q1.x) + (q2.x + q3.x);
            a1 += (q0.y + q1.y) + (q2.y + q3.y);
            a2 += (q0.z + q1.z) + (q2.z + q3.z);
            a3 += (q0.w + q1.w) + (q2.w + q3.w);
        }

        s += fmaf(w0, a0, fmaf(w1, a1, fmaf(w2, a2, w3 * a3)));
    }

    // ---- warp reduce ----
#pragma unroll
    for (int off = 16; off > 0; off >>= 1)
        s += __shfl_down_sync(0xFFFFFFFFu, s, off);
    if (lane == 0) warp_sums[wid] = s;
    __syncthreads();

    if (tid == 0) {
        float bsum = warp_sums[0];
#pragma unroll
        for (int i = 1; i < NWARP; i++) bsum += warp_sums[i];

        atomicAdd(&g_slots[blockIdx.x & (NSLOT - 1)], (double)bsum);
        __threadfence();
        unsigned old = atomicAdd(&g_count, 1u);
        if (old == NBLK - 1u) {
            __threadfence();
            double total = 0.0;
            volatile double* vs = g_slots;
#pragma unroll
            for (int i = 0; i < NSLOT; i++) {
                total += vs[i];
                vs[i] = 0.0;                 // reset for next graph replay
            }
            out[0] = (float)total;
            __threadfence();
            g_count = 0u;
        }
    }
}

extern "C" void kernel_launch(void* const* d_in, const int* in_sizes, int n_in,
                              void* d_out, int out_size) {
    const float* data  = (const float*)d_in[0];  // (16,1280,1280) fp32
    const int*   boxes = (const int*)d_in[1];    // (64,4) int32 [x1,y1,x2,y2]
    float*       out   = (float*)d_out;

    fused_kernel<<<NBLK, NTHR>>>(data, boxes, out);
}

// round 14
// speedup vs baseline: 1.2255x; 1.0089x over previous
#include <cuda_runtime.h>
#include <cstdint>

// Fixed shapes
#define TT    16
#define NPRE  4                  // frames prefetched into registers
#define NCP   (TT - NPRE)        // 12 frames staged via cp.async -> smem
#define HH    1280
#define WW    1280
#define NB    64
#define W4    (WW / 4)           // 320 float4 per row
#define HW4   (HH * W4)          // 409,600 float4 per frame
#define NTHR  W4                 // 320 threads: one float4 (4 cols) per thread
#define NBLK  HH                 // one block per row
#define NWARP (NTHR / 32)        // 10 warps
#define NSLOT 32

__device__ double       g_slots[NSLOT];   // zeroed at load; reset by last block each replay
__device__ unsigned int g_count = 0u;

__device__ __forceinline__ unsigned smem_u32(const void* p) {
    unsigned a;
    asm("{ .reg .u64 t; cvta.to.shared.u64 t, %1; cvt.u32.u64 %0, t; }" : "=r"(a) : "l"(p));
    return a;
}

// ---------------------------------------------------------------------------
// One block per row y. All 16 frame-loads in flight at once:
//   - 4 frames -> registers (LDG.128 prefetch)
//   - 12 frames -> smem via cp.async.cg (LDGSTS: no register cost, issued
//     before the scan; each thread waits only its own group, no barrier)
// Weight scan (diff array + block prefix) overlaps the copies.
// ---------------------------------------------------------------------------
__global__ void __launch_bounds__(NTHR, 3) fused_kernel(const float* __restrict__ data,
                                                        const int*   __restrict__ boxes,
                                                        float* __restrict__ out) {
    __shared__ __align__(16) float sbuf[NCP * WW];    // 61,440 B
    __shared__ int   sdiff[WW];                       //  5,120 B
    __shared__ int   wsum[NWARP];
    __shared__ float warp_sums[NWARP];

    const int tid  = threadIdx.x;        // 0..319
    const int y    = blockIdx.x;         // row
    const int lane = tid & 31;
    const int wid  = tid >> 5;

    // ---- prefetch 4 frames into registers ----
    const float4* p = reinterpret_cast<const float4*>(data) + (size_t)y * W4 + tid;
    float4 v0 = __ldg(p + 0 * (size_t)HW4);
    float4 v1 = __ldg(p + 1 * (size_t)HW4);
    float4 v2 = __ldg(p + 2 * (size_t)HW4);
    float4 v3 = __ldg(p + 3 * (size_t)HW4);

    // ---- issue 12 cp.async copies (16B each) — zero register cost ----
    {
        const unsigned dst0 = smem_u32(sbuf) + tid * 16u;
        const float4*  src  = p + (size_t)NPRE * HW4;
#pragma unroll
        for (int f = 0; f < NCP; f++) {
            asm volatile("cp.async.cg.shared.global [%0], [%1], 16;"
                         :: "r"(dst0 + f * (WW * 4u)),
                            "l"(src + (size_t)f * HW4)
                         : "memory");
        }
        asm volatile("cp.async.commit_group;" ::: "memory");
    }

    // ---- weight scan overlapped with the copies ----
    reinterpret_cast<int4*>(sdiff)[tid] = make_int4(0, 0, 0, 0);
    __syncthreads();

    if (tid < NB) {
        int4 b = __ldg(reinterpret_cast<const int4*>(boxes) + tid);  // x1,y1,x2,y2
        if (b.y <= y && y < b.w) {
            atomicAdd(&sdiff[b.x],  1);
            atomicAdd(&sdiff[b.z], -1);      // x2 <= 1279 < WW
        }
    }
    __syncthreads();

    int4 c = reinterpret_cast<const int4*>(sdiff)[tid];
    int s0 = c.x, s1 = s0 + c.y, s2 = s1 + c.z, s3 = s2 + c.w;
    const int tot = s3;

    int v = tot;
#pragma unroll
    for (int off = 1; off < 32; off <<= 1) {
        int n = __shfl_up_sync(0xFFFFFFFFu, v, off);
        if (lane >= off) v += n;
    }
    if (lane == 31) wsum[wid] = v;
    __syncthreads();

    int wprefix = 0;
#pragma unroll
    for (int i = 0; i < NWARP; i++)
        if (i < wid) wprefix += wsum[i];
    const int base = wprefix + (v - tot);    // exclusive prefix before this thread

    const float w0 = (float)(base + s0);
    const float w1 = (float)(base + s1);
    const float w2 = (float)(base + s2);
    const float w3 = (float)(base + s3);

    // ---- fold register-prefetched frames ----
    float a0 = (v0.x + v1.x) + (v2.x + v3.x);
    float a1 = (v0.y + v1.y) + (v2.y + v3.y);
    float a2 = (v0.z + v1.z) + (v2.z + v3.z);
    float a3 = (v0.w + v1.w) + (v2.w + v3.w);

    // ---- wait own copies, consume from smem (conflict-free LDS.128) ----
    asm volatile("cp.async.wait_group 0;" ::: "memory");
    const float4* sb = reinterpret_cast<const float4*>(sbuf);
    float b0 = 0.f, b1 = 0.f, b2 = 0.f, b3 = 0.f;
#pragma unroll
    for (int f = 0; f < NCP; f += 2) {
        float4 qa = sb[(f + 0) * W4 + tid];
        float4 qb = sb[(f + 1) * W4 + tid];
        a0 += qa.x; a1 += qa.y; a2 += qa.z; a3 += qa.w;
        b0 += qb.x; b1 += qb.y; b2 += qb.z; b3 += qb.w;
    }

    float s = fmaf(w0, a0 + b0, fmaf(w1, a1 + b1, fmaf(w2, a2 + b2, w3 * (a3 + b3))));

    // ---- warp + block reduce ----
#pragma unroll
    for (int off = 16; off > 0; off >>= 1)
        s += __shfl_down_sync(0xFFFFFFFFu, s, off);
    if (lane == 0) warp_sums[wid] = s;
    __syncthreads();

    if (tid == 0) {
        float bsum = warp_sums[0];
#pragma unroll
        for (int i = 1; i < NWARP; i++) bsum += warp_sums[i];

        atomicAdd(&g_slots[y & (NSLOT - 1)], (double)bsum);
        __threadfence();
        unsigned old = atomicAdd(&g_count, 1u);
        if (old == NBLK - 1u) {
            __threadfence();
            double total = 0.0;
            volatile double* vs = g_slots;
#pragma unroll
            for (int i = 0; i < NSLOT; i++) {
                total += vs[i];
                vs[i] = 0.0;                 // reset for next graph replay
            }
            out[0] = (float)total;
            __threadfence();
            g_count = 0u;
        }
    }
}

extern "C" void kernel_launch(void* const* d_in, const int* in_sizes, int n_in,
                              void* d_out, int out_size) {
    const float* data  = (const float*)d_in[0];  // (16,1280,1280) fp32
    const int*   boxes = (const int*)d_in[1];    // (64,4) int32 [x1,y1,x2,y2]
    float*       out   = (float*)d_out;

    fused_kernel<<<NBLK, NTHR>>>(data, boxes, out);
}

// round 15
// speedup vs baseline: 1.2445x; 1.0155x over previous
#include <cuda_runtime.h>
#include <cstdint>

// Fixed shapes
#define TT    16
#define HH    1280
#define WW    1280
#define NB    64
#define W4    (WW / 4)            // 320 float4 per row
#define HW4   (HH * W4)           // 409,600 float4 per frame
#define RPB   2                   // rows per block, processed in PARALLEL
#define NTHR  (W4 * RPB)          // 640 threads
#define NBLK  (HH / RPB)          // 640 blocks
#define NWARP (NTHR / 32)         // 20 warps
#define HWARP (NWARP / RPB)       // 10 warps per row-group
#define NSLOT 32

__device__ double       g_slots[NSLOT];   // zeroed at load; reset by last block each replay
__device__ unsigned int g_count = 0u;

// ---------------------------------------------------------------------------
// Block = 2 rows in PARALLEL: threads 0-319 -> row 2b, 320-639 -> row 2b+1.
// Each 320-thread group is exactly the R6 streaming engine (prefetch 4 LDG.128,
// diff-array scan overlapped, 3x4 batched remainder). Dual-bank sdiff lets both
// rows share one barrier sequence; one reduce + one slot-atomic per block.
// ---------------------------------------------------------------------------
__global__ void __launch_bounds__(NTHR, 3) fused_kernel(const float* __restrict__ data,
                                                        const int*   __restrict__ boxes,
                                                        float* __restrict__ out) {
    __shared__ int   sdiff[RPB * WW];     // two banks
    __shared__ int   wsum[NWARP];         // per-warp scan totals (banked by group)
    __shared__ float warp_sums[NWARP];

    const int tid  = threadIdx.x;         // 0..639
    const int half = tid >= W4;           // row-group 0/1
    const int ltid = tid - half * W4;     // 0..319 within group
    const int lane = tid & 31;
    const int wid  = tid >> 5;            // 0..19
    const int hwid = wid - half * HWARP;  // 0..9 within group
    const int y    = blockIdx.x * RPB + half;

    // ---- boxes first (off the critical path), one load per group ----
    int4 bx = make_int4(0, 0, 0, 0);
    if (ltid < NB) bx = __ldg(reinterpret_cast<const int4*>(boxes) + ltid); // x1,y1,x2,y2

    // ---- prefetch 4 frames (in flight through the scan phase) ----
    const float4* p = reinterpret_cast<const float4*>(data) + (size_t)y * W4 + ltid;
    float4 v0 = __ldg(p + 0 * (size_t)HW4);
    float4 v1 = __ldg(p + 1 * (size_t)HW4);
    float4 v2 = __ldg(p + 2 * (size_t)HW4);
    float4 v3 = __ldg(p + 3 * (size_t)HW4);

    // ---- weights: dual-bank difference array + per-group block scan ----
    int* bank = sdiff + half * WW;
    reinterpret_cast<int4*>(bank)[ltid] = make_int4(0, 0, 0, 0);
    __syncthreads();

    if (ltid < NB && bx.y <= y && y < bx.w) {
        atomicAdd(&bank[bx.x],  1);
        atomicAdd(&bank[bx.z], -1);       // x2 <= 1279 < WW
    }
    __syncthreads();

    int4 c = reinterpret_cast<const int4*>(bank)[ltid];
    int s0 = c.x, s1 = s0 + c.y, s2 = s1 + c.z, s3 = s2 + c.w;
    const int tot = s3;

    int v = tot;
#pragma unroll
    for (int off = 1; off < 32; off <<= 1) {
        int n = __shfl_up_sync(0xFFFFFFFFu, v, off);
        if (lane >= off) v += n;
    }
    if (lane == 31) wsum[wid] = v;
    __syncthreads();

    int wprefix = 0;
#pragma unroll
    for (int i = 0; i < HWARP; i++)
        if (i < hwid) wprefix += wsum[half * HWARP + i];
    const int base = wprefix + (v - tot); // exclusive prefix before this thread

    const float w0 = (float)(base + s0);
    const float w1 = (float)(base + s1);
    const float w2 = (float)(base + s2);
    const float w3 = (float)(base + s3);

    // ---- fold prefetched frames ----
    float a0 = (v0.x + v1.x) + (v2.x + v3.x);
    float a1 = (v0.y + v1.y) + (v2.y + v3.y);
    float a2 = (v0.z + v1.z) + (v2.z + v3.z);
    float a3 = (v0.w + v1.w) + (v2.w + v3.w);

    // ---- remaining 12 frames: 3 batches of 4 independent loads ----
#pragma unroll
    for (int t = 4; t < TT; t += 4) {
        float4 q0 = __ldg(p + (size_t)(t + 0) * HW4);
        float4 q1 = __ldg(p + (size_t)(t + 1) * HW4);
        float4 q2 = __ldg(p + (size_t)(t + 2) * HW4);
        float4 q3 = __ldg(p + (size_t)(t + 3) * HW4);
        a0 += (q0.x + q1.x) + (q2.x + q3.x);
        a1 += (q0.y + q1.y) + (q2.y + q3.y);
        a2 += (q0.z + q1.z) + (q2.z + q3.z);
        a3 += (q0.w + q1.w) + (q2.w + q3.w);
    }

    float s = fmaf(w0, a0, fmaf(w1, a1, fmaf(w2, a2, w3 * a3)));

    // ---- warp reduce (both rows fold into one block scalar) ----
#pragma unroll
    for (int off = 16; off > 0; off >>= 1)
        s += __shfl_down_sync(0xFFFFFFFFu, s, off);
    if (lane == 0) warp_sums[wid] = s;
    __syncthreads();

    if (tid == 0) {
        float bsum = warp_sums[0];
#pragma unroll
        for (int i = 1; i < NWARP; i++) bsum += warp_sums[i];

        atomicAdd(&g_slots[blockIdx.x & (NSLOT - 1)], (double)bsum);
        __threadfence();
        unsigned old = atomicAdd(&g_count, 1u);
        if (old == NBLK - 1u) {
            __threadfence();
            double total = 0.0;
            volatile double* vs = g_slots;
#pragma unroll
            for (int i = 0; i < NSLOT; i++) {
                total += vs[i];
                vs[i] = 0.0;                  // reset for next graph replay
            }
            out[0] = (float)total;
            __threadfence();
            g_count = 0u;
        }
    }
}

extern "C" void kernel_launch(void* const* d_in, const int* in_sizes, int n_in,
                              void* d_out, int out_size) {
    const float* data  = (const float*)d_in[0];  // (16,1280,1280) fp32
    const int*   boxes = (const int*)d_in[1];    // (64,4) int32 [x1,y1,x2,y2]
    float*       out   = (float*)d_out;

    fused_kernel<<<NBLK, NTHR>>>(data, boxes, out);
}